// round 16
// baseline (speedup 1.0000x reference)
#include <cuda_runtime.h>
#include <math.h>

#define B_ 8
#define T_ 4096
#define D_ 1024
#define NCHUNK 128
#define CH (T_ / NCHUNK)        // 32 rows per block
#define NBLK (B_ * NCHUNK)      // 1024 blocks
#define THREADS 256             // 4 d-lanes per thread
#define G 8                     // rows per barrier group

// Scratch (allocation-free rule: device globals)
__device__ float2 g_agg[NBLK * D_];   // per-chunk aggregate (sum_x, sum_sq)
__device__ float2 g_pre[NBLK * D_];   // per-chunk inclusive prefix
__device__ int    g_flag[NBLK];       // 0=none, 1=aggregate ready, 2=prefix ready
__device__ float  g_scal[8];          // tau, w, a1, a3, sig1, sig3, s2p, invN

__device__ __forceinline__ float tanh_fast(float x) {
    float y; asm("tanh.approx.f32 %0, %1;" : "=f"(y) : "f"(x)); return y;
}
__device__ __forceinline__ float ex2_fast(float x) {
    float y; asm("ex2.approx.f32 %0, %1;" : "=f"(y) : "f"(x)); return y;
}
__device__ __forceinline__ float lg2_fast(float x) {
    float y; asm("lg2.approx.f32 %0, %1;" : "=f"(y) : "f"(x)); return y;
}

// ---------------------------------------------------------------------------
// Kernel 0: init — block 0 computes global scalars, blocks 1..4 zero flags.
// Must run before k_fused every launch (flags are consumed destructively).
// ---------------------------------------------------------------------------
__global__ void k_init(const float* __restrict__ ema_out,
                       const float* __restrict__ var_fast,
                       const float* __restrict__ var_slow,
                       const float* __restrict__ lt,  const float* __restrict__ ls1,
                       const float* __restrict__ ls2, const float* __restrict__ ls3,
                       const float* __restrict__ lw,  const float* __restrict__ la1,
                       const float* __restrict__ la2, const float* __restrict__ la3) {
    int tid = threadIdx.x;
    if (blockIdx.x != 0) {
        int i = (blockIdx.x - 1) * THREADS + tid;
        if (i < NBLK) g_flag[i] = 0;
        return;
    }
    __shared__ float shr[8], she[8];
    float r = 0.f, e = 0.f;
    #pragma unroll
    for (int i = 0; i < 4; i++) {
        int d = tid + i * 256;
        r += fminf(var_fast[d] / fmaxf(var_slow[d], 1e-4f), 10.0f);
        float ev = ema_out[d];
        e = fmaf(ev, ev, e);
    }
    #pragma unroll
    for (int o = 16; o; o >>= 1) {
        r += __shfl_xor_sync(0xffffffffu, r, o);
        e += __shfl_xor_sync(0xffffffffu, e, o);
    }
    if ((tid & 31) == 0) { shr[tid >> 5] = r; she[tid >> 5] = e; }
    __syncthreads();
    if (tid == 0) {
        float rs = 0.f, es = 0.f;
        #pragma unroll
        for (int i = 0; i < 8; i++) { rs += shr[i]; es += she[i]; }
        float tau  = expf(lt[0]);
        float sig1 = log1pf(expf(ls1[0]));
        float sig2 = log1pf(expf(ls2[0]));
        float sig3 = log1pf(expf(ls3[0]));
        float w    = log1pf(expf(lw[0]));
        float a1   = log1pf(expf(la1[0]));
        float a2   = log1pf(expf(la2[0]));
        float a3   = log1pf(expf(la3[0]));
        float burst = fmaxf(rs / (float)D_ - 1.0f, 0.0f);
        float surp2 = tanhf(sig2 * burst);
        float s2p   = powf(fmaxf(surp2, 1e-7f), a2);
        g_scal[0] = tau;  g_scal[1] = w;    g_scal[2] = a1;  g_scal[3] = a3;
        g_scal[4] = sig1; g_scal[5] = sig3; g_scal[6] = s2p;
        g_scal[7] = 1.0f / fmaxf(sqrtf(es), 1e-12f);
    }
}

// ---------------------------------------------------------------------------
// Kernel 1: fully fused — chunk sums + decoupled lookback + main pass.
// Phase-2 x re-read hits L2 (chunk is 128 KB, published moments earlier).
// ---------------------------------------------------------------------------
__global__ void __launch_bounds__(THREADS, 4) k_fused(
        const float4* __restrict__ x,
        const float* __restrict__ ema_mean,
        const float* __restrict__ ema_sq,
        const float* __restrict__ ema_out,
        float4* __restrict__ out) {
    __shared__ float4 sG[G][THREADS];    // gelu values, 32 KB
    __shared__ float4 smA[G][32];        // per-row partials (s1,s3,dt,nm)
    __shared__ int    s_flag;
    int blk = blockIdx.x, tid = threadIdx.x;
    int c = blk & (NCHUNK - 1);
    int lane = tid & 31, wid = tid >> 5;

    float tau  = g_scal[0], w    = g_scal[1], a1  = g_scal[2], a3   = g_scal[3];
    float sig1 = g_scal[4], sig3 = g_scal[5], s2p = g_scal[6], invN = g_scal[7];
    float ws2p = w * s2p;

    long base = (long)blk * CH * (D_ / 4);
    int ci = blk * (D_ / 2) + tid * 2;   // float4 index into g_agg/g_pre

    // ---------------- phase 1: chunk sums (DRAM read of x) ----------------
    float sx[4] = {0.f, 0.f, 0.f, 0.f}, sq[4] = {0.f, 0.f, 0.f, 0.f};
    #pragma unroll 8
    for (int r = 0; r < CH; r++) {
        float4 v = x[base + (long)r * (D_ / 4) + tid];
        sx[0] += v.x; sx[1] += v.y; sx[2] += v.z; sx[3] += v.w;
        sq[0] = fmaf(v.x, v.x, sq[0]); sq[1] = fmaf(v.y, v.y, sq[1]);
        sq[2] = fmaf(v.z, v.z, sq[2]); sq[3] = fmaf(v.w, v.w, sq[3]);
    }

    // publish aggregate (readable by deeper lookbacks) — not needed for c=0/127
    if (c != 0 && c != NCHUNK - 1) {
        ((float4*)g_agg)[ci]     = make_float4(sx[0], sq[0], sx[1], sq[1]);
        ((float4*)g_agg)[ci + 1] = make_float4(sx[2], sq[2], sx[3], sq[3]);
        __threadfence();
        __syncthreads();
        if (tid == 0) atomicExch(&g_flag[blk], 1);
    }

    // ---------------- decoupled lookback: exclusive prefix ----------------
    float rx[4] = {0.f, 0.f, 0.f, 0.f}, rq[4] = {0.f, 0.f, 0.f, 0.f};
    if (c != 0) {
        int look = blk - 1;
        while (true) {
            if (tid == 0) {
                int f;
                do { f = atomicOr(&g_flag[look], 0); if (!f) __nanosleep(40); } while (f == 0);
                s_flag = f;
            }
            __syncthreads();
            int f = s_flag;
            __threadfence();
            int li = look * (D_ / 2) + tid * 2;
            const float4* src = (f == 2) ? (const float4*)g_pre : (const float4*)g_agg;
            float4 v0 = src[li];
            float4 v1 = src[li + 1];
            rx[0] += v0.x; rq[0] += v0.y; rx[1] += v0.z; rq[1] += v0.w;
            rx[2] += v1.x; rq[2] += v1.y; rx[3] += v1.z; rq[3] += v1.w;
            if (f == 2) break;
            look--;
            __syncthreads();    // protect s_flag before rewrite
        }
    }
    // publish inclusive prefix (not needed for the last chunk of a batch)
    if (c != NCHUNK - 1) {
        ((float4*)g_pre)[ci]     = make_float4(rx[0] + sx[0], rq[0] + sq[0],
                                               rx[1] + sx[1], rq[1] + sq[1]);
        ((float4*)g_pre)[ci + 1] = make_float4(rx[2] + sx[2], rq[2] + sq[2],
                                               rx[3] + sx[3], rq[3] + sq[3]);
        __threadfence();
        __syncthreads();
        if (tid == 0) atomicExch(&g_flag[blk], 2);
    }

    // ---------------- phase 2: main pass (x re-read from L2) --------------
    int d0 = tid * 4;
    float A[4], Bc[4], EN[4];
    #pragma unroll
    for (int j = 0; j < 4; j++) {
        float m = ema_mean[d0 + j];
        float v = fmaxf(ema_sq[d0 + j] - m * m, 1e-4f);
        float rs = 1.0f / (sqrtf(v) + 1e-5f);
        A[j]  = rs;
        Bc[j] = -m * rs;
        EN[j] = ema_out[d0 + j] * invN;
    }
    float cumx[4], cumsq[4];
    #pragma unroll
    for (int j = 0; j < 4; j++) { cumx[j] = rx[j]; cumsq[j] = rq[j]; }

    int t0 = c * CH;
    for (int g = 0; g < CH / G; g++) {
        // ---------- phase A: element math, gelu -> smem, 3-level reduce ----
        #pragma unroll
        for (int r = 0; r < G; r++) {
            int t = t0 + g * G + r;
            float tf  = (float)t;
            float c5  = 1e-5f * tf;
            float tt4 = (t > 0) ? 1e-4f * tf * tf : 1.0f;   // t=0 -> z3 term 0

            float4 xv = x[base + (long)(g * G + r) * (D_ / 4) + tid];
            float xe[4] = { xv.x, xv.y, xv.z, xv.w };
            float gv[4];
            float s1 = 0.f, s3 = 0.f, dt = 0.f, nm = 0.f;
            #pragma unroll
            for (int j = 0; j < 4; j++) {
                float xx = xe[j];
                float x2 = xx * xx;
                float q  = fmaf(0.0356774081363f, x2, 0.7978845608028654f);
                float th = tanh_fast(xx * q);
                float h  = 0.5f * xx;
                float gg = fmaf(h, th, h);
                gv[j] = gg;
                s1 += fabsf(fmaf(xx, A[j], Bc[j]));
                float P = cumx[j], Q = cumsq[j];
                float dd = fmaf(xx, tf, -P);
                float wv = fmaxf(fmaf(-P, P, tf * Q), tt4);
                float rr = rsqrtf(wv);
                float f  = fmaf(-c5, rr, 1.0f) * rr;
                s3 = fmaf(fabsf(dd), f, s3);
                dt = fmaf(gg, EN[j], dt);
                nm = fmaf(gg, gg, nm);
                cumx[j]  = P + xx;
                cumsq[j] = Q + x2;
            }
            sG[r][tid] = make_float4(gv[0], gv[1], gv[2], gv[3]);
            #pragma unroll
            for (int o = 16; o >= 4; o >>= 1) {
                s1 += __shfl_xor_sync(0xffffffffu, s1, o);
                s3 += __shfl_xor_sync(0xffffffffu, s3, o);
                dt += __shfl_xor_sync(0xffffffffu, dt, o);
                nm += __shfl_xor_sync(0xffffffffu, nm, o);
            }
            if (lane < 4)
                smA[r][wid * 4 + lane] = make_float4(s1, s3, dt, nm);
        }
        __syncthreads();

        // ---------- phase B+C: warp `wid` owns row `wid` completely --------
        {
            float4 v = smA[wid][lane];
            #pragma unroll
            for (int o = 16; o; o >>= 1) {
                v.x += __shfl_xor_sync(0xffffffffu, v.x, o);
                v.y += __shfl_xor_sync(0xffffffffu, v.y, o);
                v.z += __shfl_xor_sync(0xffffffffu, v.z, o);
                v.w += __shfl_xor_sync(0xffffffffu, v.w, o);
            }
            float surp1 = tanh_fast(sig1 * v.x * (1.0f / (float)D_));
            float surp3 = tanh_fast(sig3 * v.y * (1.0f / (float)D_));
            float cs = v.z * rsqrtf(fmaxf(v.w, 1e-24f));
            cs = fminf(fmaxf(cs, -1.0f), 1.0f);
            float gcos = ex2_fast(-1.4426950408889634f * tau * cs);
            float p1 = ex2_fast(a1 * lg2_fast(fmaxf(surp1, 1e-7f)));
            float p3 = ex2_fast(a3 * lg2_fast(fmaxf(surp3, 1e-7f)));
            float gate = gcos * fmaf(ws2p, p1 * p3, 1.0f);

            long rowo = base + (long)(g * G + wid) * (D_ / 4);
            #pragma unroll
            for (int k = 0; k < 8; k++) {
                int idx = lane + k * 32;
                float4 gg = sG[wid][idx];
                out[rowo + idx] = make_float4(gg.x * gate, gg.y * gate,
                                              gg.z * gate, gg.w * gate);
            }
        }
        __syncthreads();   // protect sG/smA before next group's phase A
    }
}

// ---------------------------------------------------------------------------
extern "C" void kernel_launch(void* const* d_in, const int* in_sizes, int n_in,
                              void* d_out, int out_size) {
    const float* x        = (const float*)d_in[0];
    const float* ema_mean = (const float*)d_in[1];
    const float* ema_sq   = (const float*)d_in[2];
    const float* ema_out  = (const float*)d_in[3];
    const float* var_fast = (const float*)d_in[4];
    const float* var_slow = (const float*)d_in[5];

    k_init<<<1 + (NBLK + THREADS - 1) / THREADS, THREADS>>>(
        ema_out, var_fast, var_slow,
        (const float*)d_in[6],  (const float*)d_in[7],
        (const float*)d_in[8],  (const float*)d_in[9],
        (const float*)d_in[10], (const float*)d_in[11],
        (const float*)d_in[12], (const float*)d_in[13]);
    k_fused<<<NBLK, THREADS>>>((const float4*)x, ema_mean, ema_sq, ema_out,
                               (float4*)d_out);
}

// round 17
// speedup vs baseline: 1.2811x; 1.2811x over previous
#include <cuda_runtime.h>
#include <math.h>

#define B_ 8
#define T_ 4096
#define D_ 1024
#define NCHUNK 128
#define CH (T_ / NCHUNK)        // 32 rows per k_main block
#define NBLK (B_ * NCHUNK)      // 1024 k_main blocks
#define NSUB 128                // scan sub-chunks (32 rows each)
#define CH2 (T_ / NSUB)         // 32 rows per k_partial block
#define NBLK2 (B_ * NSUB)       // 1024 k_partial blocks
#define THREADS 256             // 4 d-lanes per thread
#define G 8                     // rows per barrier group

// Scratch (allocation-free rule: device globals)
__device__ float2 g_cum[NBLK2 * D_];   // (sum_x, sum_sq) per (sub-chunk, d)
__device__ float  g_scal[8];           // tau, w, a1, a3, sig1, sig3, s2p, invN

__device__ __forceinline__ float tanh_fast(float x) {
    float y; asm("tanh.approx.f32 %0, %1;" : "=f"(y) : "f"(x)); return y;
}
__device__ __forceinline__ float ex2_fast(float x) {
    float y; asm("ex2.approx.f32 %0, %1;" : "=f"(y) : "f"(x)); return y;
}
__device__ __forceinline__ float lg2_fast(float x) {
    float y; asm("lg2.approx.f32 %0, %1;" : "=f"(y) : "f"(x)); return y;
}

// ---------------------------------------------------------------------------
// Kernel 1: per-sub-chunk sums of x and x^2; block 0 also computes scalars
// (round-8 winner: 26 us @ 66% DRAM) — now with streaming loads
// ---------------------------------------------------------------------------
__global__ void __launch_bounds__(THREADS) k_partial(
        const float4* __restrict__ x,
        const float* __restrict__ ema_out,
        const float* __restrict__ var_fast,
        const float* __restrict__ var_slow,
        const float* __restrict__ lt,  const float* __restrict__ ls1,
        const float* __restrict__ ls2, const float* __restrict__ ls3,
        const float* __restrict__ lw,  const float* __restrict__ la1,
        const float* __restrict__ la2, const float* __restrict__ la3) {
    int blk = blockIdx.x;
    int tid = threadIdx.x;
    long base = (long)blk * CH2 * (D_ / 4) + tid;
    float sx0 = 0.f, sx1 = 0.f, sx2 = 0.f, sx3 = 0.f;
    float sq0 = 0.f, sq1 = 0.f, sq2 = 0.f, sq3 = 0.f;
    #pragma unroll 8
    for (int r = 0; r < CH2; r++) {
        float4 v = __ldcs(&x[base + (long)r * (D_ / 4)]);
        sx0 += v.x; sx1 += v.y; sx2 += v.z; sx3 += v.w;
        sq0 = fmaf(v.x, v.x, sq0); sq1 = fmaf(v.y, v.y, sq1);
        sq2 = fmaf(v.z, v.z, sq2); sq3 = fmaf(v.w, v.w, sq3);
    }
    int ci = blk * (D_ / 2) + tid * 2;
    ((float4*)g_cum)[ci]     = make_float4(sx0, sq0, sx1, sq1);
    ((float4*)g_cum)[ci + 1] = make_float4(sx2, sq2, sx3, sq3);

    if (blk == 0) {
        __shared__ float shr[8], she[8];
        float r = 0.f, e = 0.f;
        #pragma unroll
        for (int i = 0; i < 4; i++) {
            int d = tid + i * 256;
            r += fminf(var_fast[d] / fmaxf(var_slow[d], 1e-4f), 10.0f);
            float ev = ema_out[d];
            e = fmaf(ev, ev, e);
        }
        #pragma unroll
        for (int o = 16; o; o >>= 1) {
            r += __shfl_xor_sync(0xffffffffu, r, o);
            e += __shfl_xor_sync(0xffffffffu, e, o);
        }
        if ((tid & 31) == 0) { shr[tid >> 5] = r; she[tid >> 5] = e; }
        __syncthreads();
        if (tid == 0) {
            float rs = 0.f, es = 0.f;
            #pragma unroll
            for (int i = 0; i < 8; i++) { rs += shr[i]; es += she[i]; }
            float tau  = expf(lt[0]);
            float sig1 = log1pf(expf(ls1[0]));
            float sig2 = log1pf(expf(ls2[0]));
            float sig3 = log1pf(expf(ls3[0]));
            float w    = log1pf(expf(lw[0]));
            float a1   = log1pf(expf(la1[0]));
            float a2   = log1pf(expf(la2[0]));
            float a3   = log1pf(expf(la3[0]));
            float burst = fmaxf(rs / (float)D_ - 1.0f, 0.0f);
            float surp2 = tanhf(sig2 * burst);
            float s2p   = powf(fmaxf(surp2, 1e-7f), a2);
            g_scal[0] = tau;  g_scal[1] = w;    g_scal[2] = a1;  g_scal[3] = a3;
            g_scal[4] = sig1; g_scal[5] = sig3; g_scal[6] = s2p;
            g_scal[7] = 1.0f / fmaxf(sqrtf(es), 1e-12f);
        }
    }
}

// ---------------------------------------------------------------------------
// Kernel 2: in-place exclusive scan over sub-chunks, per (b, d)
// ---------------------------------------------------------------------------
__global__ void k_scan() {
    int idx = blockIdx.x * blockDim.x + threadIdx.x;
    int b = idx >> 10;
    int d = idx & (D_ - 1);
    float rx = 0.f, rq = 0.f;
    int base = b * NSUB * D_ + d;
    for (int c0 = 0; c0 < NSUB; c0 += 8) {
        float2 tv[8];
        #pragma unroll
        for (int k = 0; k < 8; k++) tv[k] = g_cum[base + (c0 + k) * D_];
        #pragma unroll
        for (int k = 0; k < 8; k++) {
            g_cum[base + (c0 + k) * D_] = make_float2(rx, rq);
            rx += tv[k].x; rq += tv[k].y;
        }
    }
}

// ---------------------------------------------------------------------------
// Kernel 3: main fused pass (round-8 structure) + streaming hints + 1-deep
// load pipeline across rows and across the group barrier.
// ---------------------------------------------------------------------------
__global__ void __launch_bounds__(THREADS, 4) k_main(const float4* __restrict__ x,
                                                     const float* __restrict__ ema_mean,
                                                     const float* __restrict__ ema_sq,
                                                     const float* __restrict__ ema_out,
                                                     float4* __restrict__ out) {
    __shared__ float4 sG[G][THREADS];    // gelu values, 32 KB
    __shared__ float4 smA[G][32];        // per-row 32 partials of (s1,s3,dt,nm)
    int blk = blockIdx.x, tid = threadIdx.x;
    int c = blk & (NCHUNK - 1);
    int lane = tid & 31, wid = tid >> 5;

    float tau  = g_scal[0], w    = g_scal[1], a1  = g_scal[2], a3   = g_scal[3];
    float sig1 = g_scal[4], sig3 = g_scal[5], s2p = g_scal[6], invN = g_scal[7];
    float ws2p = w * s2p;

    int d0 = tid * 4;
    float A[4], Bc[4], EN[4], cumx[4], cumsq[4];
    #pragma unroll
    for (int j = 0; j < 4; j++) {
        float m = ema_mean[d0 + j];
        float v = fmaxf(ema_sq[d0 + j] - m * m, 1e-4f);
        float rs = 1.0f / (sqrtf(v) + 1e-5f);
        A[j]  = rs;
        Bc[j] = -m * rs;
        EN[j] = ema_out[d0 + j] * invN;
    }
    {   // exclusive prefix at this block's first row (sub-chunk == chunk)
        int ci = blk * (D_ / 2) + tid * 2;
        float4 c01 = ((const float4*)g_cum)[ci];
        float4 c23 = ((const float4*)g_cum)[ci + 1];
        cumx[0] = c01.x; cumsq[0] = c01.y; cumx[1] = c01.z; cumsq[1] = c01.w;
        cumx[2] = c23.x; cumsq[2] = c23.y; cumx[3] = c23.z; cumsq[3] = c23.w;
    }

    long base = (long)blk * CH * (D_ / 4);
    int t0 = c * CH;

    // 1-deep pipeline: xv_pre always holds row (gi+1)'s data while row gi computes
    float4 xv_pre = __ldcs(&x[base + tid]);

    for (int g = 0; g < CH / G; g++) {
        // ---------- phase A: element math, gelu -> smem, 3-level reduce ----
        #pragma unroll
        for (int r = 0; r < G; r++) {
            int gi = g * G + r;
            int t = t0 + gi;
            float tf  = (float)t;
            float c5  = 1e-5f * tf;
            float tt4 = (t > 0) ? 1e-4f * tf * tf : 1.0f;   // t=0 -> z3 term 0

            float4 xv = xv_pre;
            if (gi + 1 < CH)
                xv_pre = __ldcs(&x[base + (long)(gi + 1) * (D_ / 4) + tid]);

            float xe[4] = { xv.x, xv.y, xv.z, xv.w };
            float gv[4];
            float s1 = 0.f, s3 = 0.f, dt = 0.f, nm = 0.f;
            #pragma unroll
            for (int j = 0; j < 4; j++) {
                float xx = xe[j];
                float x2 = xx * xx;
                float q  = fmaf(0.0356774081363f, x2, 0.7978845608028654f);
                float th = tanh_fast(xx * q);
                float h  = 0.5f * xx;
                float gg = fmaf(h, th, h);
                gv[j] = gg;
                s1 += fabsf(fmaf(xx, A[j], Bc[j]));
                float P = cumx[j], Q = cumsq[j];
                float dd = fmaf(xx, tf, -P);
                float wv = fmaxf(fmaf(-P, P, tf * Q), tt4);
                float rr = rsqrtf(wv);
                float f  = fmaf(-c5, rr, 1.0f) * rr;
                s3 = fmaf(fabsf(dd), f, s3);
                dt = fmaf(gg, EN[j], dt);
                nm = fmaf(gg, gg, nm);
                cumx[j]  = P + xx;
                cumsq[j] = Q + x2;
            }
            sG[r][tid] = make_float4(gv[0], gv[1], gv[2], gv[3]);
            #pragma unroll
            for (int o = 16; o >= 4; o >>= 1) {
                s1 += __shfl_xor_sync(0xffffffffu, s1, o);
                s3 += __shfl_xor_sync(0xffffffffu, s3, o);
                dt += __shfl_xor_sync(0xffffffffu, dt, o);
                nm += __shfl_xor_sync(0xffffffffu, nm, o);
            }
            if (lane < 4)
                smA[r][wid * 4 + lane] = make_float4(s1, s3, dt, nm);
        }
        __syncthreads();

        // ---------- phase B+C: warp `wid` owns row `wid` completely --------
        {
            float4 v = smA[wid][lane];
            #pragma unroll
            for (int o = 16; o; o >>= 1) {
                v.x += __shfl_xor_sync(0xffffffffu, v.x, o);
                v.y += __shfl_xor_sync(0xffffffffu, v.y, o);
                v.z += __shfl_xor_sync(0xffffffffu, v.z, o);
                v.w += __shfl_xor_sync(0xffffffffu, v.w, o);
            }
            float surp1 = tanh_fast(sig1 * v.x * (1.0f / (float)D_));
            float surp3 = tanh_fast(sig3 * v.y * (1.0f / (float)D_));
            float cs = v.z * rsqrtf(fmaxf(v.w, 1e-24f));
            cs = fminf(fmaxf(cs, -1.0f), 1.0f);
            float gcos = ex2_fast(-1.4426950408889634f * tau * cs);
            float p1 = ex2_fast(a1 * lg2_fast(fmaxf(surp1, 1e-7f)));
            float p3 = ex2_fast(a3 * lg2_fast(fmaxf(surp3, 1e-7f)));
            float gate = gcos * fmaf(ws2p, p1 * p3, 1.0f);

            long rowo = base + (long)(g * G + wid) * (D_ / 4);
            #pragma unroll
            for (int k = 0; k < 8; k++) {
                int idx = lane + k * 32;
                float4 gg = sG[wid][idx];
                __stcs(&out[rowo + idx], make_float4(gg.x * gate, gg.y * gate,
                                                     gg.z * gate, gg.w * gate));
            }
        }
        __syncthreads();   // protect sG/smA before next group's phase A
    }
}

// ---------------------------------------------------------------------------
extern "C" void kernel_launch(void* const* d_in, const int* in_sizes, int n_in,
                              void* d_out, int out_size) {
    const float* x        = (const float*)d_in[0];
    const float* ema_mean = (const float*)d_in[1];
    const float* ema_sq   = (const float*)d_in[2];
    const float* ema_out  = (const float*)d_in[3];
    const float* var_fast = (const float*)d_in[4];
    const float* var_slow = (const float*)d_in[5];

    k_partial<<<NBLK2, THREADS>>>((const float4*)x, ema_out, var_fast, var_slow,
                                  (const float*)d_in[6],  (const float*)d_in[7],
                                  (const float*)d_in[8],  (const float*)d_in[9],
                                  (const float*)d_in[10], (const float*)d_in[11],
                                  (const float*)d_in[12], (const float*)d_in[13]);
    k_scan<<<(B_ * D_) / 256, 256>>>();
    k_main<<<NBLK, THREADS>>>((const float4*)x, ema_mean, ema_sq, ema_out, (float4*)d_out);
}